// round 2
// baseline (speedup 1.0000x reference)
#include <cuda_runtime.h>
#include <math.h>

#define NN 100000
#define EE 3200000
#define DIN 128
#define HH 64
#define NEG_INF (-1e30f)

// ---------------- device scratch (no allocation allowed) ----------------
__device__ int   g_deg[NN];
__device__ int   g_fill[NN];
__device__ int   g_rowptr[NN + 1];
__device__ int   g_csr[EE];
__device__ float g_dinv[NN];
__device__ float g_bufA[(size_t)NN * HH];
__device__ float g_bufB[(size_t)NN * HH];
__device__ float g_s5[NN];
__device__ float g_logits[NN + 1];
__device__ float g_accum[HH];
__device__ float g_blockmax[128];
__device__ float g_gmax;
__device__ float g_gsum;

// ---------------- graph prep ----------------
__global__ void init_kernel() {
    int i = blockIdx.x * blockDim.x + threadIdx.x;
    if (i < NN) { g_deg[i] = 0; g_fill[i] = 0; }
    if (i < HH) g_accum[i] = 0.f;
    if (i == 0) g_gsum = 0.f;
}

__global__ void count_kernel(const int* __restrict__ rows) {
    int e = blockIdx.x * blockDim.x + threadIdx.x;
    if (e < EE) atomicAdd(&g_deg[rows[e]], 1);
}

__global__ void dinv_kernel() {
    int i = blockIdx.x * blockDim.x + threadIdx.x;
    if (i < NN) g_dinv[i] = rsqrtf((float)(g_deg[i] + 1));  // +1 self loop
}

// single-block exclusive scan over g_deg -> g_rowptr
__global__ void scan_kernel() {
    __shared__ int sh[1024];
    int t = threadIdx.x;
    const int CH = (NN + 1023) / 1024;  // 98
    int beg = t * CH;
    int end = min(beg + CH, NN);
    int s = 0;
    for (int i = beg; i < end; i++) s += g_deg[i];
    sh[t] = s;
    __syncthreads();
    for (int off = 1; off < 1024; off <<= 1) {
        int v = (t >= off) ? sh[t - off] : 0;
        __syncthreads();
        sh[t] += v;
        __syncthreads();
    }
    int run = sh[t] - s;  // exclusive prefix
    for (int i = beg; i < end; i++) { g_rowptr[i] = run; run += g_deg[i]; }
    if (t == 1023) g_rowptr[NN] = sh[1023];
}

__global__ void fill_kernel(const int* __restrict__ rows, const int* __restrict__ cols) {
    int e = blockIdx.x * blockDim.x + threadIdx.x;
    if (e < EE) {
        int r = rows[e];
        int p = g_rowptr[r] + atomicAdd(&g_fill[r], 1);
        g_csr[p] = cols[e];
    }
}

// ---------------- GEMM: Out[i][c] = dinv[i] * sum_k Hin[i][k]*W[k][c] ----------------
template <int K>
__global__ __launch_bounds__(256) void gemm_scale(const float* __restrict__ Hin,
                                                  const float* __restrict__ W,
                                                  float* __restrict__ Out) {
    __shared__ float Ws[K * 64];
    __shared__ float Xs[32 * 65];
    int tid = threadIdx.x;
    for (int i = tid; i < K * 64; i += 256) Ws[i] = W[i];  // Ws[k*64+c]

    int r  = tid & 31;
    int cg = tid >> 5;       // 0..7
    int c0 = cg * 8;
    const int NT = (NN + 31) / 32;
    for (int tile = blockIdx.x; tile < NT; tile += gridDim.x) {
        int row0 = tile * 32;
        float acc[8];
#pragma unroll
        for (int j = 0; j < 8; j++) acc[j] = 0.f;
        for (int kc = 0; kc < K; kc += 64) {
            __syncthreads();
            for (int i = tid; i < 32 * 64; i += 256) {
                int rr = i >> 6, kk = i & 63;
                int row = row0 + rr;
                Xs[rr * 65 + kk] = (row < NN) ? Hin[(size_t)row * K + kc + kk] : 0.f;
            }
            __syncthreads();
#pragma unroll
            for (int k = 0; k < 64; k++) {
                float xv = Xs[r * 65 + k];
                const float4* wrow = (const float4*)&Ws[(kc + k) * 64 + c0];
                float4 w0 = wrow[0];
                float4 w1 = wrow[1];
                acc[0] += xv * w0.x; acc[1] += xv * w0.y;
                acc[2] += xv * w0.z; acc[3] += xv * w0.w;
                acc[4] += xv * w1.x; acc[5] += xv * w1.y;
                acc[6] += xv * w1.z; acc[7] += xv * w1.w;
            }
        }
        int row = row0 + r;
        if (row < NN) {
            float di = g_dinv[row];
            float4 o0 = make_float4(di * acc[0], di * acc[1], di * acc[2], di * acc[3]);
            float4 o1 = make_float4(di * acc[4], di * acc[5], di * acc[6], di * acc[7]);
            *(float4*)&Out[(size_t)row * 64 + c0]     = o0;
            *(float4*)&Out[(size_t)row * 64 + c0 + 4] = o1;
        }
    }
}

// ---------------- aggregation: warp per row, no atomics ----------------
__global__ __launch_bounds__(256) void agg64(const float* __restrict__ lin_s,
                                             const float* __restrict__ b,
                                             float* __restrict__ out, int relu) {
    int w = (blockIdx.x * blockDim.x + threadIdx.x) >> 5;
    int lane = threadIdx.x & 31;
    if (w >= NN) return;
    int beg = g_rowptr[w], end = g_rowptr[w + 1];
    float a0 = lin_s[w * 64 + lane];        // self-loop term (already dinv-scaled)
    float a1 = lin_s[w * 64 + 32 + lane];
    int e = beg;
    for (; e + 2 <= end; e += 2) {
        int c0 = g_csr[e], c1 = g_csr[e + 1];
        float p0 = lin_s[c0 * 64 + lane];
        float p1 = lin_s[c0 * 64 + 32 + lane];
        float q0 = lin_s[c1 * 64 + lane];
        float q1 = lin_s[c1 * 64 + 32 + lane];
        a0 += p0 + q0;
        a1 += p1 + q1;
    }
    if (e < end) {
        int c = g_csr[e];
        a0 += lin_s[c * 64 + lane];
        a1 += lin_s[c * 64 + 32 + lane];
    }
    float di = g_dinv[w];
    float o0 = di * a0 + b[lane];
    float o1 = di * a1 + b[lane + 32];
    if (relu) { o0 = fmaxf(o0, 0.f); o1 = fmaxf(o1, 0.f); }
    out[w * 64 + lane]      = o0;
    out[w * 64 + 32 + lane] = o1;
}

// ---------------- heads ----------------
__global__ void mean_kernel(const float* __restrict__ h) {
    __shared__ float sacc[64];
    int t = threadIdx.x;  // 256
    if (t < 64) sacc[t] = 0.f;
    __syncthreads();
    int c = t & 63;
    float a = 0.f;
    for (int r = blockIdx.x * 4 + (t >> 6); r < NN; r += gridDim.x * 4)
        a += h[(size_t)r * 64 + c];
    atomicAdd(&sacc[c], a);
    __syncthreads();
    if (t < 64) atomicAdd(&g_accum[t], sacc[t]);
}

__global__ __launch_bounds__(256) void dot5_kernel(const float* __restrict__ h,
                                                   const float* __restrict__ W5) {
    int w = (blockIdx.x * blockDim.x + threadIdx.x) >> 5;
    int lane = threadIdx.x & 31;
    if (w >= NN) return;
    float d = h[w * 64 + lane] * W5[lane] + h[w * 64 + 32 + lane] * W5[lane + 32];
#pragma unroll
    for (int off = 16; off > 0; off >>= 1) d += __shfl_down_sync(0xffffffff, d, off);
    if (lane == 0) g_s5[w] = g_dinv[w] * d;
}

__global__ void agg5_kernel(const float* __restrict__ b5, const int* __restrict__ ready) {
    int i = blockIdx.x * blockDim.x + threadIdx.x;
    if (i >= NN) return;
    float acc = g_s5[i];
    int beg = g_rowptr[i], end = g_rowptr[i + 1];
    for (int e = beg; e < end; e++) acc += g_s5[g_csr[e]];
    float logit = g_dinv[i] * acc + b5[0];
    g_logits[i] = (ready[i] != 0) ? logit : NEG_INF;
}

__global__ void finalize_kernel(const float* __restrict__ Wdn, const float* __restrict__ bdn,
                                const float* __restrict__ Wv, const float* __restrict__ bv,
                                float* __restrict__ out) {
    __shared__ float s1[64], s2[64];
    int t = threadIdx.x;  // 64
    float xm = g_accum[t] * (1.0f / NN);
    s1[t] = xm * Wv[t];
    s2[t] = xm * Wdn[t];
    __syncthreads();
    if (t == 0) {
        float v = 0.f, pn = 0.f;
        for (int i = 0; i < 64; i++) { v += s1[i]; pn += s2[i]; }
        out[NN + 1]  = v + bv[0];
        g_logits[NN] = pn + bdn[0];
    }
}

// ---------------- masked softmax ----------------
__global__ void max1_kernel() {
    __shared__ float sm[256];
    float m = -3.4e38f;
    for (int i = blockIdx.x * blockDim.x + threadIdx.x; i < NN + 1; i += gridDim.x * blockDim.x)
        m = fmaxf(m, g_logits[i]);
    sm[threadIdx.x] = m;
    __syncthreads();
    for (int s = 128; s > 0; s >>= 1) {
        if (threadIdx.x < s) sm[threadIdx.x] = fmaxf(sm[threadIdx.x], sm[threadIdx.x + s]);
        __syncthreads();
    }
    if (threadIdx.x == 0) g_blockmax[blockIdx.x] = sm[0];
}

__global__ void max2_kernel(int nblocks) {
    __shared__ float sm[128];
    float m = -3.4e38f;
    for (int i = threadIdx.x; i < nblocks; i += 128) m = fmaxf(m, g_blockmax[i]);
    sm[threadIdx.x] = m;
    __syncthreads();
    for (int s = 64; s > 0; s >>= 1) {
        if (threadIdx.x < s) sm[threadIdx.x] = fmaxf(sm[threadIdx.x], sm[threadIdx.x + s]);
        __syncthreads();
    }
    if (threadIdx.x == 0) g_gmax = sm[0];
}

__global__ void expsum_kernel(float* __restrict__ out) {
    __shared__ float sm[256];
    float gm = g_gmax;
    float s = 0.f;
    for (int i = blockIdx.x * blockDim.x + threadIdx.x; i < NN + 1; i += gridDim.x * blockDim.x) {
        float e = expf(g_logits[i] - gm);
        out[i] = e;
        s += e;
    }
    sm[threadIdx.x] = s;
    __syncthreads();
    for (int st = 128; st > 0; st >>= 1) {
        if (threadIdx.x < st) sm[threadIdx.x] += sm[threadIdx.x + st];
        __syncthreads();
    }
    if (threadIdx.x == 0) atomicAdd(&g_gsum, sm[0]);
}

__global__ void norm_kernel(float* __restrict__ out) {
    int i = blockIdx.x * blockDim.x + threadIdx.x;
    if (i <= NN) out[i] *= (1.0f / g_gsum);
}

// ---------------- launch ----------------
extern "C" void kernel_launch(void* const* d_in, const int* in_sizes, int n_in,
                              void* d_out, int out_size) {
    (void)in_sizes; (void)n_in; (void)out_size;
    const float* x     = (const float*)d_in[0];
    const int*   ei    = (const int*)d_in[1];      // [2, E]
    const int*   ready = (const int*)d_in[2];
    const float* W1 = (const float*)d_in[3];
    const float* b1 = (const float*)d_in[4];
    const float* W2 = (const float*)d_in[5];
    const float* b2 = (const float*)d_in[6];
    const float* W3 = (const float*)d_in[7];
    const float* b3 = (const float*)d_in[8];
    const float* W4 = (const float*)d_in[9];
    const float* b4 = (const float*)d_in[10];
    const float* W5 = (const float*)d_in[11];
    const float* b5 = (const float*)d_in[12];
    const float* Wdn = (const float*)d_in[13];
    const float* bdn = (const float*)d_in[14];
    const float* Wv  = (const float*)d_in[15];
    const float* bv  = (const float*)d_in[16];
    float* out = (float*)d_out;

    const int* rows = ei;
    const int* cols = ei + EE;

    const int NB_N = (NN + 255) / 256;       // 391
    const int NB_E = (EE + 255) / 256;       // 12500
    const int NB_W = (NN * 32 + 255) / 256;  // 12500 (warp per row)

    // graph prep
    init_kernel<<<NB_N, 256>>>();
    count_kernel<<<NB_E, 256>>>(rows);
    dinv_kernel<<<NB_N, 256>>>();
    scan_kernel<<<1, 1024>>>();
    fill_kernel<<<NB_E, 256>>>(rows, cols);

    // layer 1: x[N,128] @ W1 -> scaled lin (A), aggregate -> h1 (B)
    gemm_scale<DIN><<<740, 256>>>(x, W1, g_bufA);
    agg64<<<NB_W, 256>>>(g_bufA, b1, g_bufB, 1);
    // layers 2-4
    gemm_scale<HH><<<740, 256>>>(g_bufB, W2, g_bufA);
    agg64<<<NB_W, 256>>>(g_bufA, b2, g_bufB, 1);
    gemm_scale<HH><<<740, 256>>>(g_bufB, W3, g_bufA);
    agg64<<<NB_W, 256>>>(g_bufA, b3, g_bufB, 1);
    gemm_scale<HH><<<740, 256>>>(g_bufB, W4, g_bufA);
    agg64<<<NB_W, 256>>>(g_bufA, b4, g_bufB, 1);   // h4 in B

    // heads
    mean_kernel<<<256, 256>>>(g_bufB);
    dot5_kernel<<<NB_W, 256>>>(g_bufB, W5);
    agg5_kernel<<<NB_N, 256>>>(b5, ready);
    finalize_kernel<<<1, 64>>>(Wdn, bdn, Wv, bv, out);

    // masked softmax over N+1 logits
    max1_kernel<<<96, 256>>>();
    max2_kernel<<<1, 128>>>(96);
    expsum_kernel<<<96, 256>>>(out);
    norm_kernel<<<NB_N, 256>>>(out);
}

// round 3
// speedup vs baseline: 1.1775x; 1.1775x over previous
#include <cuda_runtime.h>
#include <math.h>

#define NN 100000
#define EE 3200000
#define DIN 128
#define HH 64
#define NEG_INF (-1e30f)

// ---------------- device scratch (no allocation allowed) ----------------
__device__ int   g_deg[NN];
__device__ int   g_fill[NN];
__device__ int   g_rowptr[NN + 1];
__device__ int   g_csr[EE];
__device__ float g_dinv[NN];
__device__ float g_bufA[(size_t)NN * HH];
__device__ float g_bufB[(size_t)NN * HH];
__device__ float g_s5[NN];
__device__ float g_logits[NN + 1];
__device__ float g_accum[HH];
__device__ float g_blockmax[128];
__device__ float g_gmax;
__device__ float g_gsum;

// ---------------- graph prep ----------------
__global__ void init_kernel() {
    int i = blockIdx.x * blockDim.x + threadIdx.x;
    if (i < NN) { g_deg[i] = 0; g_fill[i] = 0; }
    if (i < HH) g_accum[i] = 0.f;
    if (i == 0) g_gsum = 0.f;
}

__global__ void count_kernel(const int* __restrict__ rows) {
    int e = blockIdx.x * blockDim.x + threadIdx.x;
    if (e < EE) atomicAdd(&g_deg[rows[e]], 1);
}

// single-block exclusive scan over g_deg -> g_rowptr, fused dinv
__global__ void scan_kernel() {
    __shared__ int sh[1024];
    int t = threadIdx.x;
    const int CH = (NN + 1023) / 1024;  // 98
    int beg = t * CH;
    int end = min(beg + CH, NN);
    int s = 0;
    for (int i = beg; i < end; i++) s += g_deg[i];
    sh[t] = s;
    __syncthreads();
    for (int off = 1; off < 1024; off <<= 1) {
        int v = (t >= off) ? sh[t - off] : 0;
        __syncthreads();
        sh[t] += v;
        __syncthreads();
    }
    int run = sh[t] - s;  // exclusive prefix
    for (int i = beg; i < end; i++) {
        int d = g_deg[i];
        g_rowptr[i] = run;
        run += d;
        g_dinv[i] = rsqrtf((float)(d + 1));  // +1 self loop
    }
    if (t == 1023) g_rowptr[NN] = sh[1023];
}

__global__ void fill_kernel(const int* __restrict__ rows, const int* __restrict__ cols) {
    int e = blockIdx.x * blockDim.x + threadIdx.x;
    if (e < EE) {
        int r = rows[e];
        int p = g_rowptr[r] + atomicAdd(&g_fill[r], 1);
        g_csr[p] = cols[e];
    }
}

// ---------------- GEMM: Out[i][c] = dinv[i] * sum_k Hin[i][k]*W[k][c] ----------------
template <int K>
__global__ __launch_bounds__(256) void gemm_scale(const float* __restrict__ Hin,
                                                  const float* __restrict__ W,
                                                  float* __restrict__ Out) {
    __shared__ float Ws[K * 64];
    __shared__ float Xs[32 * 65];
    int tid = threadIdx.x;
    for (int i = tid; i < K * 64; i += 256) Ws[i] = W[i];  // Ws[k*64+c]

    int r  = tid & 31;
    int cg = tid >> 5;       // 0..7
    int c0 = cg * 8;
    const int NT = (NN + 31) / 32;
    for (int tile = blockIdx.x; tile < NT; tile += gridDim.x) {
        int row0 = tile * 32;
        float acc[8];
#pragma unroll
        for (int j = 0; j < 8; j++) acc[j] = 0.f;
        for (int kc = 0; kc < K; kc += 64) {
            __syncthreads();
            for (int i = tid; i < 32 * 64; i += 256) {
                int rr = i >> 6, kk = i & 63;
                int row = row0 + rr;
                Xs[rr * 65 + kk] = (row < NN) ? Hin[(size_t)row * K + kc + kk] : 0.f;
            }
            __syncthreads();
#pragma unroll
            for (int k = 0; k < 64; k++) {
                float xv = Xs[r * 65 + k];
                const float4* wrow = (const float4*)&Ws[(kc + k) * 64 + c0];
                float4 w0 = wrow[0];
                float4 w1 = wrow[1];
                acc[0] += xv * w0.x; acc[1] += xv * w0.y;
                acc[2] += xv * w0.z; acc[3] += xv * w0.w;
                acc[4] += xv * w1.x; acc[5] += xv * w1.y;
                acc[6] += xv * w1.z; acc[7] += xv * w1.w;
            }
        }
        int row = row0 + r;
        if (row < NN) {
            float di = g_dinv[row];
            float4 o0 = make_float4(di * acc[0], di * acc[1], di * acc[2], di * acc[3]);
            float4 o1 = make_float4(di * acc[4], di * acc[5], di * acc[6], di * acc[7]);
            *(float4*)&Out[(size_t)row * 64 + c0]     = o0;
            *(float4*)&Out[(size_t)row * 64 + c0 + 4] = o1;
        }
    }
}

// ---------------- aggregation v2: warp per row, half-warp per edge, float4 ----------------
// lin_s rows are 256B; lane L covers columns [(L&15)*4, (L&15)*4+4).
// half = L>>4 selects which edge of a pair this lane gathers.
__global__ __launch_bounds__(256) void agg64(const float* __restrict__ lin_s,
                                             const float* __restrict__ b,
                                             float* __restrict__ out, int relu) {
    int w = (blockIdx.x * blockDim.x + threadIdx.x) >> 5;
    int lane = threadIdx.x & 31;
    if (w >= NN) return;
    int half = lane >> 4;
    int l16  = lane & 15;
    const float4* ls = (const float4*)lin_s;
    int beg = g_rowptr[w], end = g_rowptr[w + 1];

    float4 a0, a1;
    if (half == 0) a0 = ls[w * 16 + l16];                 // self-loop (dinv-scaled already)
    else           a0 = make_float4(0.f, 0.f, 0.f, 0.f);
    a1 = make_float4(0.f, 0.f, 0.f, 0.f);

    int e = beg;
    for (; e + 4 <= end; e += 4) {
        int c0 = g_csr[e + half];
        int c1 = g_csr[e + 2 + half];
        float4 v0 = ls[c0 * 16 + l16];
        float4 v1 = ls[c1 * 16 + l16];
        a0.x += v0.x; a0.y += v0.y; a0.z += v0.z; a0.w += v0.w;
        a1.x += v1.x; a1.y += v1.y; a1.z += v1.z; a1.w += v1.w;
    }
    for (; e < end; e += 2) {
        int idx = e + half;
        if (idx < end) {
            int c = g_csr[idx];
            float4 v = ls[c * 16 + l16];
            a1.x += v.x; a1.y += v.y; a1.z += v.z; a1.w += v.w;
        }
    }
    a0.x += a1.x; a0.y += a1.y; a0.z += a1.z; a0.w += a1.w;
    a0.x += __shfl_xor_sync(0xffffffffu, a0.x, 16);
    a0.y += __shfl_xor_sync(0xffffffffu, a0.y, 16);
    a0.z += __shfl_xor_sync(0xffffffffu, a0.z, 16);
    a0.w += __shfl_xor_sync(0xffffffffu, a0.w, 16);

    if (half == 0) {
        float di = g_dinv[w];
        float4 bb = ((const float4*)b)[l16];
        float4 o;
        o.x = di * a0.x + bb.x;
        o.y = di * a0.y + bb.y;
        o.z = di * a0.z + bb.z;
        o.w = di * a0.w + bb.w;
        if (relu) {
            o.x = fmaxf(o.x, 0.f); o.y = fmaxf(o.y, 0.f);
            o.z = fmaxf(o.z, 0.f); o.w = fmaxf(o.w, 0.f);
        }
        ((float4*)out)[w * 16 + l16] = o;
    }
}

// ---------------- heads ----------------
__global__ void mean_kernel(const float* __restrict__ h) {
    __shared__ float sacc[64];
    int t = threadIdx.x;  // 256
    if (t < 64) sacc[t] = 0.f;
    __syncthreads();
    int c = t & 63;
    float a = 0.f;
    for (int r = blockIdx.x * 4 + (t >> 6); r < NN; r += gridDim.x * 4)
        a += h[(size_t)r * 64 + c];
    atomicAdd(&sacc[c], a);
    __syncthreads();
    if (t < 64) atomicAdd(&g_accum[t], sacc[t]);
}

__global__ __launch_bounds__(256) void dot5_kernel(const float* __restrict__ h,
                                                   const float* __restrict__ W5) {
    int w = (blockIdx.x * blockDim.x + threadIdx.x) >> 5;
    int lane = threadIdx.x & 31;
    if (w >= NN) return;
    float d = h[w * 64 + lane] * W5[lane] + h[w * 64 + 32 + lane] * W5[lane + 32];
#pragma unroll
    for (int off = 16; off > 0; off >>= 1) d += __shfl_down_sync(0xffffffff, d, off);
    if (lane == 0) g_s5[w] = g_dinv[w] * d;
}

__global__ void agg5_kernel(const float* __restrict__ b5, const int* __restrict__ ready) {
    int i = blockIdx.x * blockDim.x + threadIdx.x;
    if (i >= NN) return;
    float acc = g_s5[i];
    int beg = g_rowptr[i], end = g_rowptr[i + 1];
    for (int e = beg; e < end; e++) acc += g_s5[g_csr[e]];
    float logit = g_dinv[i] * acc + b5[0];
    g_logits[i] = (ready[i] != 0) ? logit : NEG_INF;
}

__global__ void finalize_kernel(const float* __restrict__ Wdn, const float* __restrict__ bdn,
                                const float* __restrict__ Wv, const float* __restrict__ bv,
                                float* __restrict__ out) {
    __shared__ float s1[64], s2[64];
    int t = threadIdx.x;  // 64
    float xm = g_accum[t] * (1.0f / NN);
    s1[t] = xm * Wv[t];
    s2[t] = xm * Wdn[t];
    __syncthreads();
    if (t == 0) {
        float v = 0.f, pn = 0.f;
        for (int i = 0; i < 64; i++) { v += s1[i]; pn += s2[i]; }
        out[NN + 1]  = v + bv[0];
        g_logits[NN] = pn + bdn[0];
    }
}

// ---------------- masked softmax ----------------
__global__ void max1_kernel() {
    __shared__ float sm[256];
    float m = -3.4e38f;
    for (int i = blockIdx.x * blockDim.x + threadIdx.x; i < NN + 1; i += gridDim.x * blockDim.x)
        m = fmaxf(m, g_logits[i]);
    sm[threadIdx.x] = m;
    __syncthreads();
    for (int s = 128; s > 0; s >>= 1) {
        if (threadIdx.x < s) sm[threadIdx.x] = fmaxf(sm[threadIdx.x], sm[threadIdx.x + s]);
        __syncthreads();
    }
    if (threadIdx.x == 0) g_blockmax[blockIdx.x] = sm[0];
}

__global__ void max2_kernel(int nblocks) {
    __shared__ float sm[128];
    float m = -3.4e38f;
    for (int i = threadIdx.x; i < nblocks; i += 128) m = fmaxf(m, g_blockmax[i]);
    sm[threadIdx.x] = m;
    __syncthreads();
    for (int s = 64; s > 0; s >>= 1) {
        if (threadIdx.x < s) sm[threadIdx.x] = fmaxf(sm[threadIdx.x], sm[threadIdx.x + s]);
        __syncthreads();
    }
    if (threadIdx.x == 0) g_gmax = sm[0];
}

__global__ void expsum_kernel(float* __restrict__ out) {
    __shared__ float sm[256];
    float gm = g_gmax;
    float s = 0.f;
    for (int i = blockIdx.x * blockDim.x + threadIdx.x; i < NN + 1; i += gridDim.x * blockDim.x) {
        float e = expf(g_logits[i] - gm);
        out[i] = e;
        s += e;
    }
    sm[threadIdx.x] = s;
    __syncthreads();
    for (int st = 128; st > 0; st >>= 1) {
        if (threadIdx.x < st) sm[threadIdx.x] += sm[threadIdx.x + st];
        __syncthreads();
    }
    if (threadIdx.x == 0) atomicAdd(&g_gsum, sm[0]);
}

__global__ void norm_kernel(float* __restrict__ out) {
    int i = blockIdx.x * blockDim.x + threadIdx.x;
    if (i <= NN) out[i] *= (1.0f / g_gsum);
}

// ---------------- launch ----------------
extern "C" void kernel_launch(void* const* d_in, const int* in_sizes, int n_in,
                              void* d_out, int out_size) {
    (void)in_sizes; (void)n_in; (void)out_size;
    const float* x     = (const float*)d_in[0];
    const int*   ei    = (const int*)d_in[1];      // [2, E]
    const int*   ready = (const int*)d_in[2];
    const float* W1 = (const float*)d_in[3];
    const float* b1 = (const float*)d_in[4];
    const float* W2 = (const float*)d_in[5];
    const float* b2 = (const float*)d_in[6];
    const float* W3 = (const float*)d_in[7];
    const float* b3 = (const float*)d_in[8];
    const float* W4 = (const float*)d_in[9];
    const float* b4 = (const float*)d_in[10];
    const float* W5 = (const float*)d_in[11];
    const float* b5 = (const float*)d_in[12];
    const float* Wdn = (const float*)d_in[13];
    const float* bdn = (const float*)d_in[14];
    const float* Wv  = (const float*)d_in[15];
    const float* bv  = (const float*)d_in[16];
    float* out = (float*)d_out;

    const int* rows = ei;
    const int* cols = ei + EE;

    const int NB_N = (NN + 255) / 256;       // 391
    const int NB_E = (EE + 255) / 256;       // 12500
    const int NB_W = (NN * 32 + 255) / 256;  // 12500 (warp per row)

    // graph prep
    init_kernel<<<NB_N, 256>>>();
    count_kernel<<<NB_E, 256>>>(rows);
    scan_kernel<<<1, 1024>>>();          // also computes dinv
    fill_kernel<<<NB_E, 256>>>(rows, cols);

    // layer 1: x[N,128] @ W1 -> scaled lin (A), aggregate -> h1 (B)
    gemm_scale<DIN><<<740, 256>>>(x, W1, g_bufA);
    agg64<<<NB_W, 256>>>(g_bufA, b1, g_bufB, 1);
    // layers 2-4
    gemm_scale<HH><<<740, 256>>>(g_bufB, W2, g_bufA);
    agg64<<<NB_W, 256>>>(g_bufA, b2, g_bufB, 1);
    gemm_scale<HH><<<740, 256>>>(g_bufB, W3, g_bufA);
    agg64<<<NB_W, 256>>>(g_bufA, b3, g_bufB, 1);
    gemm_scale<HH><<<740, 256>>>(g_bufB, W4, g_bufA);
    agg64<<<NB_W, 256>>>(g_bufA, b4, g_bufB, 1);   // h4 in B

    // heads
    mean_kernel<<<256, 256>>>(g_bufB);
    dot5_kernel<<<NB_W, 256>>>(g_bufB, W5);
    agg5_kernel<<<NB_N, 256>>>(b5, ready);
    finalize_kernel<<<1, 64>>>(Wdn, bdn, Wv, bv, out);

    // masked softmax over N+1 logits
    max1_kernel<<<96, 256>>>();
    max2_kernel<<<1, 128>>>(96);
    expsum_kernel<<<96, 256>>>(out);
    norm_kernel<<<NB_N, 256>>>(out);
}